// round 8
// baseline (speedup 1.0000x reference)
#include <cuda_runtime.h>
#include <cuda_fp16.h>

#define NN 100000
#define NE 1000000
#define D  64
#define HS 68              // smem h-row stride (floats)
#define SCAN_BS 1024
#define NBLK 98            // ceil(NN/1024)

// ---------------- static scratch ----------------
__device__ __half2 g_bufA[NN * (D / 2)];
__device__ __half2 g_bufB[NN * (D / 2)];
__device__ float g_out_norm[NN];
__device__ float g_in_norm[NN];
__device__ int   g_deg_out[NN];
__device__ int   g_deg_in[NN];
__device__ int   g_row_start[NN];
__device__ int   g_fill[NN];
__device__ int   g_src_sorted[NE];
__device__ int   g_bsum[NBLK];

// ---------------- helpers ----------------
__device__ __forceinline__ unsigned long long pk2(float lo, float hi) {
    unsigned long long r;
    asm("mov.b64 %0, {%1,%2};" : "=l"(r) : "f"(lo), "f"(hi));
    return r;
}
__device__ __forceinline__ void fma2(unsigned long long& d,
                                     unsigned long long a, unsigned long long b) {
    asm("fma.rn.f32x2 %0, %1, %2, %0;" : "+l"(d) : "l"(a), "l"(b));
}
__device__ __forceinline__ float2 upk2(unsigned long long v) {
    float2 f;
    asm("mov.b64 {%0,%1}, %2;" : "=f"(f.x), "=f"(f.y) : "l"(v));
    return f;
}
__device__ __forceinline__ float2 h2f(unsigned int u) {
    float2 f;
    asm("{\n\t"
        ".reg .f16 lo, hi;\n\t"
        "mov.b32 {lo, hi}, %2;\n\t"
        "cvt.f32.f16 %0, lo;\n\t"
        "cvt.f32.f16 %1, hi;\n\t"
        "}"
        : "=f"(f.x), "=f"(f.y) : "r"(u));
    return f;
}
__device__ __forceinline__ unsigned int f2h(float a, float b) {
    unsigned int u;
    asm("{\n\t"
        ".reg .f16 lo, hi;\n\t"
        "cvt.rn.f16.f32 lo, %1;\n\t"
        "cvt.rn.f16.f32 hi, %2;\n\t"
        "mov.b32 %0, {lo, hi};\n\t"
        "}"
        : "=r"(u) : "f"(a), "f"(b));
    return u;
}
__device__ __forceinline__ void addrow(float* acc, uint4 r) {
    float2 f;
    f = h2f(r.x); acc[0] += f.x; acc[1] += f.y;
    f = h2f(r.y); acc[2] += f.x; acc[3] += f.y;
    f = h2f(r.z); acc[4] += f.x; acc[5] += f.y;
    f = h2f(r.w); acc[6] += f.x; acc[7] += f.y;
}

// ---------------- setup kernels ----------------
__global__ void zero_deg_kernel() {
    int i = blockIdx.x * blockDim.x + threadIdx.x;
    if (i < NN) { g_deg_out[i] = 0; g_deg_in[i] = 0; }
}

__global__ void count_kernel(const int* __restrict__ src, const int* __restrict__ dst) {
    int e = blockIdx.x * blockDim.x + threadIdx.x;
    if (e < NE) {
        atomicAdd(&g_deg_out[src[e]], 1);
        atomicAdd(&g_deg_in[dst[e]], 1);
    }
}

__global__ void scan1_kernel() {
    __shared__ int sh[SCAN_BS];
    int t = threadIdx.x;
    int i = blockIdx.x * SCAN_BS + t;
    int v = (i < NN) ? g_deg_in[i] : 0;
    sh[t] = v;
    __syncthreads();
#pragma unroll
    for (int off = 1; off < SCAN_BS; off <<= 1) {
        int xv = (t >= off) ? sh[t - off] : 0;
        __syncthreads();
        sh[t] += xv;
        __syncthreads();
    }
    if (i < NN) g_row_start[i] = sh[t] - v;
    if (t == SCAN_BS - 1) g_bsum[blockIdx.x] = sh[t];
}

// finalize: re-scan 98 block sums in smem, write row_start/fill/norms
__global__ void scan3_kernel() {
    __shared__ int s[128];
    int t = threadIdx.x;
    if (t < 128) s[t] = (t < NBLK) ? g_bsum[t] : 0;
    __syncthreads();
#pragma unroll
    for (int off = 1; off < 128; off <<= 1) {
        int xv = (t >= off && t < 128) ? s[t - off] : 0;
        __syncthreads();
        if (t < 128) s[t] += xv;
        __syncthreads();
    }
    int i = blockIdx.x * blockDim.x + t;
    if (i < NN) {
        int blk = i >> 10;
        int boff = (blk == 0) ? 0 : s[blk - 1];
        int rs = g_row_start[i] + boff;
        g_row_start[i] = rs;
        g_fill[i] = rs;
        int dout = g_deg_out[i]; if (dout < 1) dout = 1;
        int din  = g_deg_in[i];  if (din  < 1) din  = 1;
        g_out_norm[i] = rsqrtf((float)dout);
        g_in_norm[i]  = rsqrtf((float)din);
    }
}

__global__ void fill_kernel(const int* __restrict__ src, const int* __restrict__ dst) {
    int e = blockIdx.x * blockDim.x + threadIdx.x;
    if (e < NE) {
        int p = atomicAdd(&g_fill[dst[e]], 1);
        g_src_sorted[p] = src[e];
    }
}

__global__ void prescale_kernel(const float4* __restrict__ x) {
    int i = blockIdx.x * blockDim.x + threadIdx.x;
    if (i < NN * (D / 4)) {
        float s = g_out_norm[i >> 4];
        float4 v = __ldg(&x[i]);
        uint2 st;
        st.x = f2h(v.x * s, v.y * s);
        st.y = f2h(v.z * s, v.w * s);
        reinterpret_cast<uint2*>(g_bufA)[i] = st;
    }
}

// ---------------- fused gather + GEMM layer ----------------
// 512 threads, 32 nodes/block.
// Phase 1: 16 lanes/node = 2 octets on alternate edges (serial chain = deg/2),
//          each lane LDG.128 of a 16B fp16 slice, fp32 accumulate, shfl_xor(8).
// Phase 2: 16 warps x 2 nodes, FFMA2 GEMM from smem W.
__global__ void __launch_bounds__(512) layer_kernel(
        int in_sel, float* __restrict__ out_ext, int out_sel,
        const float* __restrict__ W, const float* __restrict__ b,
        int relu, int scale_out) {
    __shared__ float sW[D * D];      // 16KB
    __shared__ float sh[32 * HS];    // 8.7KB
    __shared__ float sb[D];

    int tid = threadIdx.x;
    for (int i = tid; i < D * D; i += 512) sW[i] = W[i];
    if (tid < D) sb[tid] = b[tid];

    const __half2* in = in_sel ? g_bufB : g_bufA;
    __half2* out_h16 = out_sel ? g_bufB : g_bufA;

    // ---- phase 1: aggregation ----
    int g   = tid >> 4;         // node slot 0..31
    int sub = (tid >> 3) & 1;   // octet 0/1
    int c8  = tid & 7;          // 16B column slice
    int node = blockIdx.x * 32 + g;   // NN % 32 == 0

    float acc[8];
#pragma unroll
    for (int j = 0; j < 8; j++) acc[j] = 0.f;

    {
        const uint4* inp = reinterpret_cast<const uint4*>(in);
        int rbeg = g_row_start[node];
        int eend = rbeg + g_deg_in[node];
        int e = rbeg + sub;             // this octet: edges sub, sub+2, sub+4, ...
        for (; e + 2 < eend; e += 4) {
            int s0 = g_src_sorted[e];
            int s1 = g_src_sorted[e + 2];
            uint4 r0 = __ldg(&inp[s0 * 8 + c8]);
            uint4 r1 = __ldg(&inp[s1 * 8 + c8]);
            addrow(acc, r0);
            addrow(acc, r1);
        }
        if (e < eend) {
            int s0 = g_src_sorted[e];
            uint4 r0 = __ldg(&inp[s0 * 8 + c8]);
            addrow(acc, r0);
        }
    }
    // merge octets
#pragma unroll
    for (int j = 0; j < 8; j++)
        acc[j] += __shfl_xor_sync(0xffffffffu, acc[j], 8);

    if (sub == 0) {
        float nrm = g_in_norm[node];
        float* dstp = &sh[g * HS + c8 * 8];
        *reinterpret_cast<float4*>(dstp) =
            make_float4(acc[0] * nrm, acc[1] * nrm, acc[2] * nrm, acc[3] * nrm);
        *reinterpret_cast<float4*>(dstp + 4) =
            make_float4(acc[4] * nrm, acc[5] * nrm, acc[6] * nrm, acc[7] * nrm);
    }
    __syncthreads();

    // ---- phase 2: GEMM (16 warps x 2 nodes, FFMA2) ----
    {
        int w = tid >> 5;         // 0..15
        int lane = tid & 31;
        int r0 = lane >> 4;       // node within warp pair
        int c2 = lane & 15;       // output col quad
        unsigned long long acc01 = 0ull, acc23 = 0ull;
        int gslot = w * 2 + r0;

#pragma unroll
        for (int kb = 0; kb < 16; kb++) {
            float4 a4 = *reinterpret_cast<const float4*>(&sh[gslot * HS + kb * 4]);
#pragma unroll
            for (int q = 0; q < 4; q++) {
                int k = kb * 4 + q;
                unsigned long long w01 =
                    *reinterpret_cast<const unsigned long long*>(&sW[k * D + c2 * 4]);
                unsigned long long w23 =
                    *reinterpret_cast<const unsigned long long*>(&sW[k * D + c2 * 4 + 2]);
                float a = (q == 0) ? a4.x : (q == 1) ? a4.y : (q == 2) ? a4.z : a4.w;
                unsigned long long aa = pk2(a, a);
                fma2(acc01, aa, w01);
                fma2(acc23, aa, w23);
            }
        }
        float b0 = sb[c2 * 4 + 0], b1 = sb[c2 * 4 + 1];
        float b2 = sb[c2 * 4 + 2], b3 = sb[c2 * 4 + 3];
        int nd = blockIdx.x * 32 + gslot;
        float2 v01 = upk2(acc01);
        float2 v23 = upk2(acc23);
        float o0 = v01.x + b0, o1 = v01.y + b1;
        float o2 = v23.x + b2, o3 = v23.y + b3;
        if (relu) {
            o0 = fmaxf(o0, 0.f); o1 = fmaxf(o1, 0.f);
            o2 = fmaxf(o2, 0.f); o3 = fmaxf(o3, 0.f);
        }
        if (scale_out) {
            float on = g_out_norm[nd];
            o0 *= on; o1 *= on; o2 *= on; o3 *= on;
        }
        if (out_ext) {
            reinterpret_cast<float4*>(out_ext)[nd * 16 + c2] =
                make_float4(o0, o1, o2, o3);
        } else {
            uint2 st;
            st.x = f2h(o0, o1);
            st.y = f2h(o2, o3);
            reinterpret_cast<uint2*>(out_h16)[nd * 16 + c2] = st;
        }
    }
}

// ---------------- launch ----------------
extern "C" void kernel_launch(void* const* d_in, const int* in_sizes, int n_in,
                              void* d_out, int out_size) {
    const float* x   = (const float*)d_in[0];
    const int*   src = (const int*)d_in[1];
    const int*   dst = (const int*)d_in[2];
    const float* W1  = (const float*)d_in[3];
    const float* b1  = (const float*)d_in[4];
    const float* W2  = (const float*)d_in[5];
    const float* b2  = (const float*)d_in[6];
    const float* W3  = (const float*)d_in[7];
    const float* b3  = (const float*)d_in[8];
    float* out = (float*)d_out;

    const int TB = 256;
    const int GN = (NN + TB - 1) / TB;
    const int GE = (NE + TB - 1) / TB;

    zero_deg_kernel<<<GN, TB>>>();
    count_kernel<<<GE, TB>>>(src, dst);
    scan1_kernel<<<NBLK, SCAN_BS>>>();
    scan3_kernel<<<GN, TB>>>();
    fill_kernel<<<GE, TB>>>(src, dst);
    prescale_kernel<<<(NN * 16 + TB - 1) / TB, TB>>>(
        reinterpret_cast<const float4*>(x));

    const int GL = NN / 32;         // 3125
    layer_kernel<<<GL, 512>>>(0, nullptr, 1, W1, b1, 1, 1);   // bufA -> bufB
    layer_kernel<<<GL, 512>>>(1, nullptr, 0, W2, b2, 1, 1);   // bufB -> bufA
    layer_kernel<<<GL, 512>>>(0, out, 0, W3, b3, 0, 0);       // bufA -> out
}

// round 9
// speedup vs baseline: 1.3677x; 1.3677x over previous
#include <cuda_runtime.h>
#include <cuda_fp16.h>

#define NN 100000
#define NE 1000000
#define D  64
#define HS 68              // smem h-row stride (floats)
#define SCAN_BS 1024
#define NBLK 98            // ceil(NN/1024)

// ---------------- static scratch ----------------
__device__ __half2 g_bufA[NN * (D / 2)];
__device__ __half2 g_bufB[NN * (D / 2)];
__device__ float g_out_norm[NN];
__device__ float g_in_norm[NN];
__device__ int   g_deg_out[NN];
__device__ int   g_deg_in[NN];
__device__ int   g_row_start[NN];
__device__ int   g_fill[NN];
__device__ int   g_src_sorted[NE];
__device__ int   g_bsum[NBLK];

// ---------------- helpers ----------------
__device__ __forceinline__ unsigned long long pk2(float lo, float hi) {
    unsigned long long r;
    asm("mov.b64 %0, {%1,%2};" : "=l"(r) : "f"(lo), "f"(hi));
    return r;
}
__device__ __forceinline__ void fma2(unsigned long long& d,
                                     unsigned long long a, unsigned long long b) {
    asm("fma.rn.f32x2 %0, %1, %2, %0;" : "+l"(d) : "l"(a), "l"(b));
}
__device__ __forceinline__ float2 upk2(unsigned long long v) {
    float2 f;
    asm("mov.b64 {%0,%1}, %2;" : "=f"(f.x), "=f"(f.y) : "l"(v));
    return f;
}
__device__ __forceinline__ float2 h2f(unsigned int u) {
    float2 f;
    asm("{\n\t"
        ".reg .f16 lo, hi;\n\t"
        "mov.b32 {lo, hi}, %2;\n\t"
        "cvt.f32.f16 %0, lo;\n\t"
        "cvt.f32.f16 %1, hi;\n\t"
        "}"
        : "=f"(f.x), "=f"(f.y) : "r"(u));
    return f;
}
__device__ __forceinline__ unsigned int f2h(float a, float b) {
    unsigned int u;
    asm("{\n\t"
        ".reg .f16 lo, hi;\n\t"
        "cvt.rn.f16.f32 lo, %1;\n\t"
        "cvt.rn.f16.f32 hi, %2;\n\t"
        "mov.b32 %0, {lo, hi};\n\t"
        "}"
        : "=r"(u) : "f"(a), "f"(b));
    return u;
}
__device__ __forceinline__ void addrow(float* acc, uint4 r) {
    float2 f;
    f = h2f(r.x); acc[0] += f.x; acc[1] += f.y;
    f = h2f(r.y); acc[2] += f.x; acc[3] += f.y;
    f = h2f(r.z); acc[4] += f.x; acc[5] += f.y;
    f = h2f(r.w); acc[6] += f.x; acc[7] += f.y;
}

// ---------------- setup kernels ----------------
__global__ void zero_deg_kernel() {
    int i = blockIdx.x * blockDim.x + threadIdx.x;
    if (i < NN) { g_deg_out[i] = 0; g_deg_in[i] = 0; }
}

__global__ void count_kernel(const int* __restrict__ src, const int* __restrict__ dst) {
    int e = blockIdx.x * blockDim.x + threadIdx.x;
    if (e < NE) {
        atomicAdd(&g_deg_out[src[e]], 1);
        atomicAdd(&g_deg_in[dst[e]], 1);
    }
}

__global__ void scan1_kernel() {
    __shared__ int sh[SCAN_BS];
    int t = threadIdx.x;
    int i = blockIdx.x * SCAN_BS + t;
    int v = (i < NN) ? g_deg_in[i] : 0;
    sh[t] = v;
    __syncthreads();
#pragma unroll
    for (int off = 1; off < SCAN_BS; off <<= 1) {
        int xv = (t >= off) ? sh[t - off] : 0;
        __syncthreads();
        sh[t] += xv;
        __syncthreads();
    }
    if (i < NN) g_row_start[i] = sh[t] - v;
    if (t == SCAN_BS - 1) g_bsum[blockIdx.x] = sh[t];
}

// finalize: re-scan 98 block sums in smem, write row_start/fill/norms
__global__ void scan3_kernel() {
    __shared__ int s[128];
    int t = threadIdx.x;
    if (t < 128) s[t] = (t < NBLK) ? g_bsum[t] : 0;
    __syncthreads();
#pragma unroll
    for (int off = 1; off < 128; off <<= 1) {
        int xv = (t >= off && t < 128) ? s[t - off] : 0;
        __syncthreads();
        if (t < 128) s[t] += xv;
        __syncthreads();
    }
    int i = blockIdx.x * blockDim.x + t;
    if (i < NN) {
        int blk = i >> 10;
        int boff = (blk == 0) ? 0 : s[blk - 1];
        int rs = g_row_start[i] + boff;
        g_row_start[i] = rs;
        g_fill[i] = rs;
        int dout = g_deg_out[i]; if (dout < 1) dout = 1;
        int din  = g_deg_in[i];  if (din  < 1) din  = 1;
        g_out_norm[i] = rsqrtf((float)dout);
        g_in_norm[i]  = rsqrtf((float)din);
    }
}

__global__ void fill_kernel(const int* __restrict__ src, const int* __restrict__ dst) {
    int e = blockIdx.x * blockDim.x + threadIdx.x;
    if (e < NE) {
        int p = atomicAdd(&g_fill[dst[e]], 1);
        g_src_sorted[p] = src[e];
    }
}

__global__ void prescale_kernel(const float4* __restrict__ x) {
    int i = blockIdx.x * blockDim.x + threadIdx.x;
    if (i < NN * (D / 4)) {
        float s = g_out_norm[i >> 4];
        float4 v = __ldg(&x[i]);
        uint2 st;
        st.x = f2h(v.x * s, v.y * s);
        st.y = f2h(v.z * s, v.w * s);
        reinterpret_cast<uint2*>(g_bufA)[i] = st;
    }
}

// ---------------- fused gather + GEMM layer ----------------
// 256 threads, 32 nodes/block (R7 layout).
// Phase 1: 8 lanes/node, lane owns one 16B fp16 slice; x4 edge unroll with
//          one-stage software-pipelined index prefetch (branch-free clamp).
// Phase 2: 8 warps x 4 nodes, FFMA2 GEMM from smem W.
__global__ void __launch_bounds__(256) layer_kernel(
        int in_sel, float* __restrict__ out_ext, int out_sel,
        const float* __restrict__ W, const float* __restrict__ b,
        int relu, int scale_out) {
    __shared__ float sW[D * D];      // 16KB
    __shared__ float sh[32 * HS];    // 8.7KB
    __shared__ float sb[D];

    int tid = threadIdx.x;
    for (int i = tid; i < D * D; i += 256) sW[i] = W[i];
    if (tid < D) sb[tid] = b[tid];

    const __half2* in = in_sel ? g_bufB : g_bufA;
    __half2* out_h16 = out_sel ? g_bufB : g_bufA;

    // ---- phase 1: aggregation ----
    int g  = tid >> 3;          // node slot 0..31
    int c8 = tid & 7;           // 16B column slice
    int node = blockIdx.x * 32 + g;   // NN % 32 == 0

    float acc[8];
#pragma unroll
    for (int j = 0; j < 8; j++) acc[j] = 0.f;

    {
        const uint4* inp = reinterpret_cast<const uint4*>(in);
        const int NEm1 = NE - 1;
        int e = g_row_start[node];
        int eend = e + g_deg_in[node];
        // prefetch first 4 indices (clamped; branch-free)
        int i0 = g_src_sorted[min(e + 0, NEm1)];
        int i1 = g_src_sorted[min(e + 1, NEm1)];
        int i2 = g_src_sorted[min(e + 2, NEm1)];
        int i3 = g_src_sorted[min(e + 3, NEm1)];
        while (e + 3 < eend) {
            uint4 r0 = __ldg(&inp[i0 * 8 + c8]);
            uint4 r1 = __ldg(&inp[i1 * 8 + c8]);
            uint4 r2 = __ldg(&inp[i2 * 8 + c8]);
            uint4 r3 = __ldg(&inp[i3 * 8 + c8]);
            e += 4;
            // prefetch next 4 indices while rows are in flight
            i0 = g_src_sorted[min(e + 0, NEm1)];
            i1 = g_src_sorted[min(e + 1, NEm1)];
            i2 = g_src_sorted[min(e + 2, NEm1)];
            i3 = g_src_sorted[min(e + 3, NEm1)];
            addrow(acc, r0);
            addrow(acc, r1);
            addrow(acc, r2);
            addrow(acc, r3);
        }
        // remainder (<=3 edges): indices already prefetched
        if (e < eend) {
            uint4 r = __ldg(&inp[i0 * 8 + c8]);
            addrow(acc, r);
        }
        if (e + 1 < eend) {
            uint4 r = __ldg(&inp[i1 * 8 + c8]);
            addrow(acc, r);
        }
        if (e + 2 < eend) {
            uint4 r = __ldg(&inp[i2 * 8 + c8]);
            addrow(acc, r);
        }
        float nrm = g_in_norm[node];
        float* dstp = &sh[g * HS + c8 * 8];
        *reinterpret_cast<float4*>(dstp) =
            make_float4(acc[0] * nrm, acc[1] * nrm, acc[2] * nrm, acc[3] * nrm);
        *reinterpret_cast<float4*>(dstp + 4) =
            make_float4(acc[4] * nrm, acc[5] * nrm, acc[6] * nrm, acc[7] * nrm);
    }
    __syncthreads();

    // ---- phase 2: GEMM (8 warps x 4 nodes, FFMA2) ----
    {
        int w = tid >> 5;
        int lane = tid & 31;
        int r0 = lane >> 4;       // 0/1
        int c2 = lane & 15;       // output col quad
        unsigned long long acc01[2], acc23[2];
#pragma unroll
        for (int m = 0; m < 2; m++) { acc01[m] = 0ull; acc23[m] = 0ull; }

#pragma unroll
        for (int kb = 0; kb < 16; kb++) {
            float4 a4[2];
#pragma unroll
            for (int m = 0; m < 2; m++)
                a4[m] = *reinterpret_cast<const float4*>(
                    &sh[(w * 4 + r0 + 2 * m) * HS + kb * 4]);
#pragma unroll
            for (int q = 0; q < 4; q++) {
                int k = kb * 4 + q;
                unsigned long long w01 =
                    *reinterpret_cast<const unsigned long long*>(&sW[k * D + c2 * 4]);
                unsigned long long w23 =
                    *reinterpret_cast<const unsigned long long*>(&sW[k * D + c2 * 4 + 2]);
#pragma unroll
                for (int m = 0; m < 2; m++) {
                    float a = (q == 0) ? a4[m].x : (q == 1) ? a4[m].y
                             : (q == 2) ? a4[m].z : a4[m].w;
                    unsigned long long aa = pk2(a, a);
                    fma2(acc01[m], aa, w01);
                    fma2(acc23[m], aa, w23);
                }
            }
        }
        float b0 = sb[c2 * 4 + 0], b1 = sb[c2 * 4 + 1];
        float b2 = sb[c2 * 4 + 2], b3 = sb[c2 * 4 + 3];
#pragma unroll
        for (int m = 0; m < 2; m++) {
            int nd = blockIdx.x * 32 + w * 4 + r0 + 2 * m;
            float2 v01 = upk2(acc01[m]);
            float2 v23 = upk2(acc23[m]);
            float o0 = v01.x + b0, o1 = v01.y + b1;
            float o2 = v23.x + b2, o3 = v23.y + b3;
            if (relu) {
                o0 = fmaxf(o0, 0.f); o1 = fmaxf(o1, 0.f);
                o2 = fmaxf(o2, 0.f); o3 = fmaxf(o3, 0.f);
            }
            if (scale_out) {
                float on = g_out_norm[nd];
                o0 *= on; o1 *= on; o2 *= on; o3 *= on;
            }
            if (out_ext) {
                reinterpret_cast<float4*>(out_ext)[nd * 16 + c2] =
                    make_float4(o0, o1, o2, o3);
            } else {
                uint2 st;
                st.x = f2h(o0, o1);
                st.y = f2h(o2, o3);
                reinterpret_cast<uint2*>(out_h16)[nd * 16 + c2] = st;
            }
        }
    }
}

// ---------------- launch ----------------
extern "C" void kernel_launch(void* const* d_in, const int* in_sizes, int n_in,
                              void* d_out, int out_size) {
    const float* x   = (const float*)d_in[0];
    const int*   src = (const int*)d_in[1];
    const int*   dst = (const int*)d_in[2];
    const float* W1  = (const float*)d_in[3];
    const float* b1  = (const float*)d_in[4];
    const float* W2  = (const float*)d_in[5];
    const float* b2  = (const float*)d_in[6];
    const float* W3  = (const float*)d_in[7];
    const float* b3  = (const float*)d_in[8];
    float* out = (float*)d_out;

    const int TB = 256;
    const int GN = (NN + TB - 1) / TB;
    const int GE = (NE + TB - 1) / TB;

    zero_deg_kernel<<<GN, TB>>>();
    count_kernel<<<GE, TB>>>(src, dst);
    scan1_kernel<<<NBLK, SCAN_BS>>>();
    scan3_kernel<<<GN, TB>>>();
    fill_kernel<<<GE, TB>>>(src, dst);
    prescale_kernel<<<(NN * 16 + TB - 1) / TB, TB>>>(
        reinterpret_cast<const float4*>(x));

    const int GL = NN / 32;         // 3125
    layer_kernel<<<GL, 256>>>(0, nullptr, 1, W1, b1, 1, 1);   // bufA -> bufB
    layer_kernel<<<GL, 256>>>(1, nullptr, 0, W2, b2, 1, 1);   // bufB -> bufA
    layer_kernel<<<GL, 256>>>(0, out, 0, W3, b3, 0, 0);       // bufA -> out
}